// round 5
// baseline (speedup 1.0000x reference)
#include <cuda_runtime.h>
#include <cuda_bf16.h>
#include <cstdint>
#include <math.h>

#define BSZ 128
#define SSZ 256
#define ISZ 1024
#define HSZ 1024
#define G4  4096
#define CSZ 1000

#define GRID2 128   // persistent recurrence grid (must be <= #SMs for co-residency)

// ---------------------------------------------------------------------------
// Device-global scratch
// ---------------------------------------------------------------------------
__device__ float g_xw[(size_t)SSZ * G4 * BSZ];              // [s][g][b] fp32
__device__ __nv_bfloat16 g_xhi[(size_t)BSZ * SSZ * ISZ];    // x split hi  [b][s][k]
__device__ __nv_bfloat16 g_xlo[(size_t)BSZ * SSZ * ISZ];
__device__ __nv_bfloat16 g_wxhi[(size_t)G4 * ISZ];
__device__ __nv_bfloat16 g_wxlo[(size_t)G4 * ISZ];
__device__ __nv_bfloat16 g_whhi[(size_t)G4 * HSZ];
__device__ __nv_bfloat16 g_whlo[(size_t)G4 * HSZ];
__device__ __nv_bfloat16 g_hhi[2][BSZ * HSZ];               // h ping-pong hi [b][k]
__device__ __nv_bfloat16 g_hlo[2][BSZ * HSZ];
__device__ unsigned g_bar_count;                            // zero-init (bss)
__device__ unsigned g_bar_gen;

// ---------------------------------------------------------------------------
// PTX helpers (sm_103 baseline: ldmatrix / mma.sync / cp.async)
// ---------------------------------------------------------------------------
__device__ __forceinline__ uint32_t smem_u32(const void* p) {
    uint32_t a;
    asm("{ .reg .u64 t; cvta.to.shared.u64 t, %1; cvt.u32.u64 %0, t; }"
        : "=r"(a) : "l"(p));
    return a;
}

#define CP16(s, g) \
    asm volatile("cp.async.cg.shared.global [%0], [%1], 16;" :: "r"(s), "l"(g))
#define CP_COMMIT() asm volatile("cp.async.commit_group;" ::: "memory")
#define CP_WAIT1()  asm volatile("cp.async.wait_group 1;" ::: "memory")

__device__ __forceinline__ void ldmx4(uint32_t* r, uint32_t addr) {
    asm volatile("ldmatrix.sync.aligned.m8n8.x4.shared.b16 {%0,%1,%2,%3}, [%4];"
        : "=r"(r[0]), "=r"(r[1]), "=r"(r[2]), "=r"(r[3]) : "r"(addr));
}

__device__ __forceinline__ void mma16816(float* d, const uint32_t* a, const uint32_t* b) {
    asm volatile(
        "mma.sync.aligned.m16n8k16.row.col.f32.bf16.bf16.f32 "
        "{%0,%1,%2,%3}, {%4,%5,%6,%7}, {%8,%9}, {%0,%1,%2,%3};"
        : "+f"(d[0]), "+f"(d[1]), "+f"(d[2]), "+f"(d[3])
        : "r"(a[0]), "r"(a[1]), "r"(a[2]), "r"(a[3]), "r"(b[0]), "r"(b[1]));
}

__device__ __forceinline__ float sigf(float x) { return 1.0f / (1.0f + __expf(-x)); }
__device__ __forceinline__ float tanh_fast(float x) {
    float e = __expf(fminf(fmaxf(2.0f * x, -30.0f), 30.0f));
    return __fdividef(e - 1.0f, e + 1.0f);
}

// ---------------------------------------------------------------------------
// split fp32 -> (hi, lo) bf16
// ---------------------------------------------------------------------------
__global__ void split_k(const float* __restrict__ src, int sel, int n4) {
    __nv_bfloat16 *hi, *lo;
    if (sel == 0)      { hi = g_xhi;  lo = g_xlo;  }
    else if (sel == 1) { hi = g_wxhi; lo = g_wxlo; }
    else               { hi = g_whhi; lo = g_whlo; }
    int i = blockIdx.x * blockDim.x + threadIdx.x;
    if (i >= n4) return;
    float4 v = reinterpret_cast<const float4*>(src)[i];
    __nv_bfloat16 h0 = __float2bfloat16(v.x), h1 = __float2bfloat16(v.y);
    __nv_bfloat16 h2 = __float2bfloat16(v.z), h3 = __float2bfloat16(v.w);
    __nv_bfloat162 a, b;
    a.x = h0; a.y = h1; b.x = h2; b.y = h3;
    reinterpret_cast<__nv_bfloat162*>(hi)[2 * i]     = a;
    reinterpret_cast<__nv_bfloat162*>(hi)[2 * i + 1] = b;
    a.x = __float2bfloat16(v.x - __bfloat162float(h0));
    a.y = __float2bfloat16(v.y - __bfloat162float(h1));
    b.x = __float2bfloat16(v.z - __bfloat162float(h2));
    b.y = __float2bfloat16(v.w - __bfloat162float(h3));
    reinterpret_cast<__nv_bfloat162*>(lo)[2 * i]     = a;
    reinterpret_cast<__nv_bfloat162*>(lo)[2 * i + 1] = b;
}

__global__ void init_state() {
    int i = blockIdx.x * blockDim.x + threadIdx.x;
    if (i < BSZ * HSZ) {
        g_hhi[0][i] = __float2bfloat16(0.0f);
        g_hlo[0][i] = __float2bfloat16(0.0f);
    }
}

// ---------------------------------------------------------------------------
// Phase 1: xw[s][g][b], M=128 (batch), N=128 gates/CTA, virtual K=3072.
// 3 smem buffers, 2 outstanding cp.async groups, 1 sync per chunk.
// ---------------------------------------------------------------------------
#define PITCH     144
#define P1_STG    36864
#define P1_BOFF   18432
#define P1_BIAS   110592
#define P1_SMEM   111104
#define NCHUNK    48

__global__ __launch_bounds__(256, 2) void gemm_xw_tc(const float* __restrict__ bxh,
                                                     const float* __restrict__ bhh) {
    extern __shared__ char sm[];
    const uint32_t sb = smem_u32(sm);
    const int tid = threadIdx.x;
    const int wid = tid >> 5, lane = tid & 31;
    const int s  = blockIdx.y;
    const int n0 = blockIdx.x * 128;

    float* sbias = reinterpret_cast<float*>(sm + P1_BIAS);
    if (tid < 128) sbias[tid] = bxh[n0 + tid] + bhh[n0 + tid];

    const int wm = wid >> 2, wn = wid & 3;
    const int lrow = tid >> 3, lq = tid & 7;

    auto load_stage = [&](int c, int buf) {
        const int seg  = c >> 4;
        const int koff = (c & 15) * 64 + lq * 8;
        const __nv_bfloat16* Asrc = (seg == 1) ? g_xlo  : g_xhi;
        const __nv_bfloat16* Bsrc = (seg == 2) ? g_wxlo : g_wxhi;
        uint32_t Ab = sb + buf * P1_STG + lrow * PITCH + lq * 16;
        uint32_t Bb = Ab + P1_BOFF;
#pragma unroll
        for (int i = 0; i < 4; i++) {
            int row = lrow + i * 32;
            CP16(Ab + i * 32 * PITCH, Asrc + (((size_t)((row << 8) + s)) << 10) + koff);
            CP16(Bb + i * 32 * PITCH, Bsrc + (((size_t)(n0 + row)) << 10) + koff);
        }
    };

    load_stage(0, 0); CP_COMMIT();
    load_stage(1, 1); CP_COMMIT();

    float d[4][4][4];
#pragma unroll
    for (int i = 0; i < 4; i++)
#pragma unroll
        for (int j = 0; j < 4; j++)
#pragma unroll
            for (int k = 0; k < 4; k++) d[i][j][k] = 0.0f;

    const uint32_t a_r = (uint32_t)(lane & 15) * PITCH + ((lane >> 4) << 4);
    const uint32_t b_r = (uint32_t)((lane & 7) + ((lane & 16) >> 1)) * PITCH
                       + (((lane >> 3) & 1) << 4);

    int buf = 0;
    for (int c = 0; c < NCHUNK; c++) {
        CP_WAIT1();
        __syncthreads();
        if (c + 2 < NCHUNK) load_stage(c + 2, (c + 2) % 3);
        CP_COMMIT();
        const uint32_t Ab = sb + buf * P1_STG;
        const uint32_t Bb = Ab + P1_BOFF;
#pragma unroll
        for (int s2 = 0; s2 < 4; s2++) {
            uint32_t a[4][4], b[2][4];
#pragma unroll
            for (int mt = 0; mt < 4; mt++)
                ldmx4(a[mt], Ab + (uint32_t)(wm * 64 + mt * 16) * PITCH + s2 * 32 + a_r);
#pragma unroll
            for (int nt = 0; nt < 2; nt++)
                ldmx4(b[nt], Bb + (uint32_t)(wn * 32 + nt * 16) * PITCH + s2 * 32 + b_r);
#pragma unroll
            for (int mt = 0; mt < 4; mt++)
#pragma unroll
                for (int n8 = 0; n8 < 4; n8++)
                    mma16816(d[mt][n8], a[mt], &b[n8 >> 1][(n8 & 1) * 2]);
        }
        buf = (buf == 2) ? 0 : buf + 1;
    }

    // epilogue: transpose through smem, coalesced writeout with bias
    __syncthreads();
    float* tile = reinterpret_cast<float*>(sm);  // [g:128][pitch 132]
    const int fr = lane >> 2, fc = (lane & 3) * 2;
#pragma unroll
    for (int mt = 0; mt < 4; mt++)
#pragma unroll
        for (int n8 = 0; n8 < 4; n8++) {
            int r0 = wm * 64 + mt * 16 + fr;
            int cc = wn * 32 + n8 * 8 + fc;
            tile[(size_t)cc * 132 + r0]           = d[mt][n8][0];
            tile[(size_t)(cc + 1) * 132 + r0]     = d[mt][n8][1];
            tile[(size_t)cc * 132 + r0 + 8]       = d[mt][n8][2];
            tile[(size_t)(cc + 1) * 132 + r0 + 8] = d[mt][n8][3];
        }
    __syncthreads();
#pragma unroll
    for (int it = 0; it < 16; it++) {
        int u = tid + it * 256;
        int g = u >> 5, q = u & 31;
        float4 v = *reinterpret_cast<const float4*>(tile + (size_t)g * 132 + q * 4);
        float bi = sbias[g];
        v.x += bi; v.y += bi; v.z += bi; v.w += bi;
        *reinterpret_cast<float4*>(g_xw + ((size_t)s * G4 + n0 + g) * BSZ + q * 4) = v;
    }
}

// ---------------------------------------------------------------------------
// Phase 2: PERSISTENT recurrence kernel. 128 CTAs loop over t with a software
// grid barrier. CTA: j = bid>>1 (16 hidden cols), mh = bid&1 (batch half).
// M=64 x N=64 x virtual K=3072 per step; c lives in registers for all steps.
// smem: stages 0..55296 | sxw 55296(+16384) | sh 71680(+4096) | total 75776
// epilogue overlays: sg f32[64][65] @0
// ---------------------------------------------------------------------------
#define P2_STG   18432
#define P2_BOFF  9216
#define P2_XW    55296
#define P2_SH    71680
#define P2_SMEM  75776

__global__ __launch_bounds__(256, 1) void lstm_persist() {
    extern __shared__ char sm[];
    const uint32_t sb = smem_u32(sm);
    const int tid = threadIdx.x;
    const int wid = tid >> 5, lane = tid & 31;
    const int bid = blockIdx.x;
    const int j  = bid >> 1;      // hidden col group (16 cols)
    const int mh = bid & 1;       // batch half

    const int wm = wid >> 2, gi = wid & 3;
    const int lrow = tid >> 3, lq = tid & 7;

    const uint32_t a_r = (uint32_t)(lane & 15) * PITCH + ((lane >> 4) << 4);
    const uint32_t b_r = (uint32_t)((lane & 7) + ((lane & 16) >> 1)) * PITCH
                       + (((lane >> 3) & 1) << 4);

    // barrier base generation (robust across graph replays)
    __shared__ unsigned s_gen;
    if (tid == 0) s_gen = *(volatile unsigned*)&g_bar_gen;
    __syncthreads();
    unsigned gen = s_gen;

    // cell state in registers: thread owns (bl = tid&63, hq = tid>>6) -> 4 hc
    const int bl = tid & 63, hq = tid >> 6;
    float cre[4] = {0.0f, 0.0f, 0.0f, 0.0f};

    float* sg  = reinterpret_cast<float*>(sm);            // [64][65] (overlays buf0)
    float* sxw = reinterpret_cast<float*>(sm + P2_XW);    // [64 gate rows][64 b]
    float* sh  = reinterpret_cast<float*>(sm + P2_SH);    // [64][16]

    for (int t = 0; t < SSZ; t++) {
        if (t > 0) {
            // -------- grid barrier: h(t) must be globally visible --------
            __syncthreads();
            if (tid == 0) {
                __threadfence();
                unsigned arrived = atomicAdd(&g_bar_count, 1u);
                if (arrived == GRID2 - 1) {
                    *(volatile unsigned*)&g_bar_count = 0;
                    __threadfence();
                    atomicAdd(&g_bar_gen, 1u);
                } else {
                    while (*(volatile unsigned*)&g_bar_gen == gen) { __nanosleep(32); }
                    __threadfence();
                }
            }
            __syncthreads();
            gen++;
        }

        const __nv_bfloat16* __restrict__ hin_hi = g_hhi[t & 1];
        const __nv_bfloat16* __restrict__ hin_lo = g_hlo[t & 1];
        __nv_bfloat16* __restrict__ hout_hi = g_hhi[(t + 1) & 1];
        __nv_bfloat16* __restrict__ hout_lo = g_hlo[(t + 1) & 1];

        auto load_stage = [&](int c, int buf) {
            const int seg  = c >> 4;
            const int koff = (c & 15) * 64 + lq * 8;
            const __nv_bfloat16* Asrc = (seg == 1) ? hin_lo : hin_hi;
            const __nv_bfloat16* Bsrc = (seg == 2) ? g_whlo : g_whhi;
            uint32_t Ab = sb + buf * P2_STG + lrow * PITCH + lq * 16;
            uint32_t Bb = Ab + P2_BOFF;
#pragma unroll
            for (int i = 0; i < 2; i++) {
                int row = lrow + i * 32;
                CP16(Ab + i * 32 * PITCH, Asrc + ((size_t)(mh * 64 + row) << 10) + koff);
                int grow = (row >> 4) * HSZ + j * 16 + (row & 15);
                CP16(Bb + i * 32 * PITCH, Bsrc + ((size_t)grow << 10) + koff);
            }
        };

        // group 0: xw slice for step t + chunk 0; group 1: chunk 1
        {
#pragma unroll
            for (int it = 0; it < 4; it++) {
                int u = tid + it * 256;
                int gg = u >> 4, q = u & 15;
                const float* src = g_xw
                    + ((size_t)t * G4 + (gg >> 4) * HSZ + j * 16 + (gg & 15)) * BSZ
                    + mh * 64 + q * 4;
                CP16(sb + P2_XW + gg * 256 + q * 16, src);
            }
            load_stage(0, 0); CP_COMMIT();
            load_stage(1, 1); CP_COMMIT();
        }

        float d[2][2][4];
#pragma unroll
        for (int i = 0; i < 2; i++)
#pragma unroll
            for (int jj = 0; jj < 2; jj++)
#pragma unroll
                for (int k = 0; k < 4; k++) d[i][jj][k] = 0.0f;

        int buf = 0;
        for (int c = 0; c < NCHUNK; c++) {
            CP_WAIT1();
            __syncthreads();
            if (c + 2 < NCHUNK) load_stage(c + 2, (c + 2) % 3);
            CP_COMMIT();
            const uint32_t Ab = sb + buf * P2_STG;
            const uint32_t Bb = Ab + P2_BOFF;
#pragma unroll
            for (int s2 = 0; s2 < 4; s2++) {
                uint32_t a[2][4], b[4];
#pragma unroll
                for (int mt = 0; mt < 2; mt++)
                    ldmx4(a[mt], Ab + (uint32_t)(wm * 32 + mt * 16) * PITCH + s2 * 32 + a_r);
                ldmx4(b, Bb + (uint32_t)(gi * 16) * PITCH + s2 * 32 + b_r);
#pragma unroll
                for (int mt = 0; mt < 2; mt++)
#pragma unroll
                    for (int n8 = 0; n8 < 2; n8++)
                        mma16816(d[mt][n8], a[mt], &b[n8 * 2]);
            }
            buf = (buf == 2) ? 0 : buf + 1;
        }

        // gates to smem: sg[b_local][gate*16 + hc] (overlays buf0; safe: the
        // slowest warp is in chunk 47 reading buf2, and all warps passed the
        // c=47 top barrier)
        const int fr = lane >> 2, fc = (lane & 3) * 2;
#pragma unroll
        for (int mt = 0; mt < 2; mt++)
#pragma unroll
            for (int n8 = 0; n8 < 2; n8++) {
                int r0 = wm * 32 + mt * 16 + fr;
                int cc = gi * 16 + n8 * 8 + fc;
                sg[(size_t)r0 * 65 + cc]           = d[mt][n8][0];
                sg[(size_t)r0 * 65 + cc + 1]       = d[mt][n8][1];
                sg[(size_t)(r0 + 8) * 65 + cc]     = d[mt][n8][2];
                sg[(size_t)(r0 + 8) * 65 + cc + 1] = d[mt][n8][3];
            }
        __syncthreads();

        // fused gate math; c in registers
#pragma unroll
        for (int ii = 0; ii < 4; ii++) {
            const int hc = hq * 4 + ii;
            float vi = sg[(size_t)bl * 65 + hc]      + sxw[(0 * 16 + hc) * 64 + bl];
            float vf = sg[(size_t)bl * 65 + 16 + hc] + sxw[(1 * 16 + hc) * 64 + bl];
            float vg = sg[(size_t)bl * 65 + 32 + hc] + sxw[(2 * 16 + hc) * 64 + bl];
            float vo = sg[(size_t)bl * 65 + 48 + hc] + sxw[(3 * 16 + hc) * 64 + bl];
            float ig = sigf(vi), fg = sigf(vf), og = sigf(vo);
            float ch = tanh_fast(vg);
            float cn = cre[ii] * fg + ig * ch;
            cre[ii] = cn;
            sh[bl * 16 + hc] = og * tanh_fast(cn);
        }
        __syncthreads();

        // h writeout: split to bf16 hi/lo, 16B stores
        if (tid < 128) {
            const int b = tid >> 1, half = tid & 1;
            const float* src = sh + b * 16 + half * 8;
            __align__(16) __nv_bfloat16 hi8[8], lo8[8];
#pragma unroll
            for (int i = 0; i < 8; i++) {
                float v = src[i];
                __nv_bfloat16 h = __float2bfloat16(v);
                hi8[i] = h;
                lo8[i] = __float2bfloat16(v - __bfloat162float(h));
            }
            size_t dst = ((size_t)(mh * 64 + b) << 10) + j * 16 + half * 8;
            *reinterpret_cast<uint4*>(hout_hi + dst) = *reinterpret_cast<const uint4*>(hi8);
            *reinterpret_cast<uint4*>(hout_lo + dst) = *reinterpret_cast<const uint4*>(lo8);
        }
    }
}

// ---------------------------------------------------------------------------
// Phase 3: out[b][c] = h_last . Wfc[c] + bfc[c]
// ---------------------------------------------------------------------------
__global__ __launch_bounds__(256) void fc_out(const float* __restrict__ Wfc,
                                              const float* __restrict__ bfc,
                                              float* __restrict__ out) {
    __shared__ float hs[HSZ];
    const int b = blockIdx.x;
    for (int i = threadIdx.x; i < HSZ; i += 256)
        hs[i] = __bfloat162float(g_hhi[0][b * HSZ + i]) + __bfloat162float(g_hlo[0][b * HSZ + i]);
    __syncthreads();

    for (int cc = threadIdx.x; cc < CSZ; cc += 256) {
        const float* wr = Wfc + (size_t)cc * HSZ;
        float acc = 0.0f;
#pragma unroll 4
        for (int k = 0; k < HSZ; k += 4) {
            float4 w = *reinterpret_cast<const float4*>(wr + k);
            acc = fmaf(hs[k + 0], w.x, acc);
            acc = fmaf(hs[k + 1], w.y, acc);
            acc = fmaf(hs[k + 2], w.z, acc);
            acc = fmaf(hs[k + 3], w.w, acc);
        }
        out[b * CSZ + cc] = acc + bfc[cc];
    }
}

// ---------------------------------------------------------------------------
// launch
// ---------------------------------------------------------------------------
extern "C" void kernel_launch(void* const* d_in, const int* in_sizes, int n_in,
                              void* d_out, int out_size) {
    const float* x   = (const float*)d_in[0];
    const float* Wxh = (const float*)d_in[1];
    const float* bxh = (const float*)d_in[2];
    const float* Whh = (const float*)d_in[3];
    const float* bhh = (const float*)d_in[4];
    const float* Wfc = (const float*)d_in[5];
    const float* bfc = (const float*)d_in[6];
    float* out = (float*)d_out;

    cudaFuncSetAttribute(gemm_xw_tc,   cudaFuncAttributeMaxDynamicSharedMemorySize, P1_SMEM);
    cudaFuncSetAttribute(lstm_persist, cudaFuncAttributeMaxDynamicSharedMemorySize, P2_SMEM);

    {
        int n4 = (BSZ * SSZ * ISZ) / 4;
        split_k<<<(n4 + 255) / 256, 256>>>(x, 0, n4);
        n4 = (G4 * ISZ) / 4;
        split_k<<<(n4 + 255) / 256, 256>>>(Wxh, 1, n4);
        n4 = (G4 * HSZ) / 4;
        split_k<<<(n4 + 255) / 256, 256>>>(Whh, 2, n4);
    }
    init_state<<<(BSZ * HSZ + 255) / 256, 256>>>();

    dim3 g1(G4 / 128, SSZ);   // (32, 256)
    gemm_xw_tc<<<g1, 256, P1_SMEM>>>(bxh, bhh);

    lstm_persist<<<GRID2, 256, P2_SMEM>>>();

    fc_out<<<BSZ, 256>>>(Wfc, bfc, out);
}

// round 6
// speedup vs baseline: 1.5670x; 1.5670x over previous
#include <cuda_runtime.h>
#include <cuda_fp16.h>
#include <cstdint>
#include <math.h>

#define BSZ 128
#define SSZ 256
#define ISZ 1024
#define HSZ 1024
#define G4  4096
#define CSZ 1000

// ---------------------------------------------------------------------------
// Device-global scratch
// ---------------------------------------------------------------------------
__device__ float g_xw[(size_t)SSZ * G4 * BSZ];        // [s][g][b] fp32
__device__ __half g_xhi[(size_t)BSZ * SSZ * ISZ];     // x split hi  [b][s][k]
__device__ __half g_xlo[(size_t)BSZ * SSZ * ISZ];
__device__ __half g_wxh[(size_t)G4 * ISZ];            // Wxh rounded to fp16
__device__ __half g_whh[(size_t)G4 * HSZ];            // Whh rounded to fp16
__device__ __half g_hhi[2][BSZ * HSZ];                // h ping-pong hi [b][k]
__device__ __half g_hlo[2][BSZ * HSZ];
__device__ float g_c[HSZ * BSZ];                      // c, [hc][b]

// ---------------------------------------------------------------------------
// PTX helpers (sm_103 baseline: ldmatrix / mma.sync / cp.async)
// ---------------------------------------------------------------------------
__device__ __forceinline__ uint32_t smem_u32(const void* p) {
    uint32_t a;
    asm("{ .reg .u64 t; cvta.to.shared.u64 t, %1; cvt.u32.u64 %0, t; }"
        : "=r"(a) : "l"(p));
    return a;
}

#define CP16(s, g) \
    asm volatile("cp.async.cg.shared.global [%0], [%1], 16;" :: "r"(s), "l"(g))
#define CP_COMMIT() asm volatile("cp.async.commit_group;" ::: "memory")
#define CP_WAIT1()  asm volatile("cp.async.wait_group 1;" ::: "memory")

__device__ __forceinline__ void ldmx4(uint32_t* r, uint32_t addr) {
    asm volatile("ldmatrix.sync.aligned.m8n8.x4.shared.b16 {%0,%1,%2,%3}, [%4];"
        : "=r"(r[0]), "=r"(r[1]), "=r"(r[2]), "=r"(r[3]) : "r"(addr));
}

__device__ __forceinline__ void mma16816(float* d, const uint32_t* a, const uint32_t* b) {
    asm volatile(
        "mma.sync.aligned.m16n8k16.row.col.f32.f16.f16.f32 "
        "{%0,%1,%2,%3}, {%4,%5,%6,%7}, {%8,%9}, {%0,%1,%2,%3};"
        : "+f"(d[0]), "+f"(d[1]), "+f"(d[2]), "+f"(d[3])
        : "r"(a[0]), "r"(a[1]), "r"(a[2]), "r"(a[3]), "r"(b[0]), "r"(b[1]));
}

__device__ __forceinline__ float sigf(float x) { return 1.0f / (1.0f + __expf(-x)); }
__device__ __forceinline__ float tanh_fast(float x) {
    float e = __expf(fminf(fmaxf(2.0f * x, -30.0f), 30.0f));
    return __fdividef(e - 1.0f, e + 1.0f);
}

// ---------------------------------------------------------------------------
// split fp32 -> (hi, lo) fp16 for x; round fp32 -> fp16 for weights
// ---------------------------------------------------------------------------
__global__ void split_x(const float* __restrict__ src, int n4) {
    int i = blockIdx.x * blockDim.x + threadIdx.x;
    if (i >= n4) return;
    float4 v = reinterpret_cast<const float4*>(src)[i];
    __half h0 = __float2half_rn(v.x), h1 = __float2half_rn(v.y);
    __half h2 = __float2half_rn(v.z), h3 = __float2half_rn(v.w);
    __half2 a, b;
    a.x = h0; a.y = h1; b.x = h2; b.y = h3;
    reinterpret_cast<__half2*>(g_xhi)[2 * i]     = a;
    reinterpret_cast<__half2*>(g_xhi)[2 * i + 1] = b;
    a.x = __float2half_rn(v.x - __half2float(h0));
    a.y = __float2half_rn(v.y - __half2float(h1));
    b.x = __float2half_rn(v.z - __half2float(h2));
    b.y = __float2half_rn(v.w - __half2float(h3));
    reinterpret_cast<__half2*>(g_xlo)[2 * i]     = a;
    reinterpret_cast<__half2*>(g_xlo)[2 * i + 1] = b;
}

__global__ void round_w(const float* __restrict__ src, int sel, int n4) {
    __half* dst = (sel == 0) ? g_wxh : g_whh;
    int i = blockIdx.x * blockDim.x + threadIdx.x;
    if (i >= n4) return;
    float4 v = reinterpret_cast<const float4*>(src)[i];
    __half2 a, b;
    a.x = __float2half_rn(v.x); a.y = __float2half_rn(v.y);
    b.x = __float2half_rn(v.z); b.y = __float2half_rn(v.w);
    reinterpret_cast<__half2*>(dst)[2 * i]     = a;
    reinterpret_cast<__half2*>(dst)[2 * i + 1] = b;
}

__global__ void init_state() {
    int i = blockIdx.x * blockDim.x + threadIdx.x;
    if (i < BSZ * HSZ) {
        g_hhi[0][i] = __float2half(0.0f);
        g_hlo[0][i] = __float2half(0.0f);
        g_c[i] = 0.0f;
    }
}

// ---------------------------------------------------------------------------
// Phase 1: xw[s][g][b], M=128 (batch), N=128 gates/CTA, virtual K=2048
// (seg0: Ah*B, seg1: Al*B). 3 smem buffers, 1 sync per chunk.
// ---------------------------------------------------------------------------
#define PITCH     144
#define P1_STG    36864
#define P1_BOFF   18432
#define P1_BIAS   110592
#define P1_SMEM   111104
#define NCHUNK    32

__global__ __launch_bounds__(256, 1) void gemm_xw_tc(const float* __restrict__ bxh,
                                                     const float* __restrict__ bhh) {
    extern __shared__ char sm[];
    const uint32_t sb = smem_u32(sm);
    const int tid = threadIdx.x;
    const int wid = tid >> 5, lane = tid & 31;
    const int s  = blockIdx.y;
    const int n0 = blockIdx.x * 128;

    float* sbias = reinterpret_cast<float*>(sm + P1_BIAS);
    if (tid < 128) sbias[tid] = bxh[n0 + tid] + bhh[n0 + tid];

    const int wm = wid >> 2, wn = wid & 3;
    const int lrow = tid >> 3, lq = tid & 7;

    auto load_stage = [&](int c, int buf) {
        const int seg  = c >> 4;
        const int koff = (c & 15) * 64 + lq * 8;
        const __half* Asrc = (seg == 1) ? g_xlo : g_xhi;
        uint32_t Ab = sb + buf * P1_STG + lrow * PITCH + lq * 16;
        uint32_t Bb = Ab + P1_BOFF;
#pragma unroll
        for (int i = 0; i < 4; i++) {
            int row = lrow + i * 32;
            CP16(Ab + i * 32 * PITCH, Asrc + (((size_t)((row << 8) + s)) << 10) + koff);
            CP16(Bb + i * 32 * PITCH, g_wxh + (((size_t)(n0 + row)) << 10) + koff);
        }
    };

    load_stage(0, 0); CP_COMMIT();
    load_stage(1, 1); CP_COMMIT();

    float d[4][4][4];
#pragma unroll
    for (int i = 0; i < 4; i++)
#pragma unroll
        for (int j = 0; j < 4; j++)
#pragma unroll
            for (int k = 0; k < 4; k++) d[i][j][k] = 0.0f;

    const uint32_t a_r = (uint32_t)(lane & 15) * PITCH + ((lane >> 4) << 4);
    const uint32_t b_r = (uint32_t)((lane & 7) + ((lane & 16) >> 1)) * PITCH
                       + (((lane >> 3) & 1) << 4);

    int buf = 0;
    for (int c = 0; c < NCHUNK; c++) {
        CP_WAIT1();
        __syncthreads();
        if (c + 2 < NCHUNK) load_stage(c + 2, (c + 2) % 3);
        CP_COMMIT();
        const uint32_t Ab = sb + buf * P1_STG;
        const uint32_t Bb = Ab + P1_BOFF;
#pragma unroll
        for (int s2 = 0; s2 < 4; s2++) {
            uint32_t a[4][4], b[2][4];
#pragma unroll
            for (int mt = 0; mt < 4; mt++)
                ldmx4(a[mt], Ab + (uint32_t)(wm * 64 + mt * 16) * PITCH + s2 * 32 + a_r);
#pragma unroll
            for (int nt = 0; nt < 2; nt++)
                ldmx4(b[nt], Bb + (uint32_t)(wn * 32 + nt * 16) * PITCH + s2 * 32 + b_r);
#pragma unroll
            for (int mt = 0; mt < 4; mt++)
#pragma unroll
                for (int n8 = 0; n8 < 4; n8++)
                    mma16816(d[mt][n8], a[mt], &b[n8 >> 1][(n8 & 1) * 2]);
        }
        buf = (buf == 2) ? 0 : buf + 1;
    }

    // epilogue: transpose through smem, coalesced writeout with bias
    __syncthreads();
    float* tile = reinterpret_cast<float*>(sm);  // [g:128][pitch 132]
    const int fr = lane >> 2, fc = (lane & 3) * 2;
#pragma unroll
    for (int mt = 0; mt < 4; mt++)
#pragma unroll
        for (int n8 = 0; n8 < 4; n8++) {
            int r0 = wm * 64 + mt * 16 + fr;
            int cc = wn * 32 + n8 * 8 + fc;
            tile[(size_t)cc * 132 + r0]           = d[mt][n8][0];
            tile[(size_t)(cc + 1) * 132 + r0]     = d[mt][n8][1];
            tile[(size_t)cc * 132 + r0 + 8]       = d[mt][n8][2];
            tile[(size_t)(cc + 1) * 132 + r0 + 8] = d[mt][n8][3];
        }
    __syncthreads();
#pragma unroll
    for (int it = 0; it < 16; it++) {
        int u = tid + it * 256;
        int g = u >> 5, q = u & 31;
        float4 v = *reinterpret_cast<const float4*>(tile + (size_t)g * 132 + q * 4);
        float bi = sbias[g];
        v.x += bi; v.y += bi; v.z += bi; v.w += bi;
        *reinterpret_cast<float4*>(g_xw + ((size_t)s * G4 + n0 + g) * BSZ + q * 4) = v;
    }
}

// ---------------------------------------------------------------------------
// Phase 2: one LSTM step. Grid (64, 2): j = 16-hidden-col group, mh = batch half.
// CTA: M=64 (batch) x N=64 (4 gates x 16 hidden), real K=1024 in 8 chunks of 128.
// Each chunk stage holds A_hi, A_lo and B (shared by both passes) -> 8 syncs/step.
// smem: 3 stages of 52224 | sxw @156672 (+16384) | sc @173056 (+4096) = 177152
// epilogue overlays: sg f32[64][65] @0, sh f32[64][16] @16640 (buf0; safe)
// ---------------------------------------------------------------------------
#define PITCH2   272
#define P2_ALO   17408
#define P2_BB    34816
#define P2_STG   52224
#define P2_XW    156672
#define P2_C     173056
#define P2_SH    16640
#define P2_SMEM  177152
#define NCH2     8

__global__ __launch_bounds__(256, 1) void lstm_tc(int t) {
    extern __shared__ char sm[];
    const uint32_t sb = smem_u32(sm);
    const int tid = threadIdx.x;
    const int wid = tid >> 5, lane = tid & 31;
    const int j = blockIdx.x;      // hidden col group (16)
    const int mh = blockIdx.y;     // batch half

    const __half* __restrict__ hin_hi = g_hhi[t & 1];
    const __half* __restrict__ hin_lo = g_hlo[t & 1];
    __half* __restrict__ hout_hi = g_hhi[(t + 1) & 1];
    __half* __restrict__ hout_lo = g_hlo[(t + 1) & 1];

    const int wm = wid >> 2, gi = wid & 3;
    const int lrow = tid >> 4, lq = tid & 15;   // 16 rows x 16 quads (256B row)

    auto load_stage = [&](int c, int buf) {
        const int koff = c * 128 + lq * 8;
        uint32_t Sb = sb + buf * P2_STG + lrow * PITCH2 + lq * 16;
#pragma unroll
        for (int i = 0; i < 4; i++) {
            int row = lrow + i * 16;
            size_t srcA = ((size_t)(mh * 64 + row) << 10) + koff;
            CP16(Sb + i * 16 * PITCH2,          hin_hi + srcA);
            CP16(Sb + P2_ALO + i * 16 * PITCH2, hin_lo + srcA);
            int grow = (row >> 4) * HSZ + j * 16 + (row & 15);
            CP16(Sb + P2_BB + i * 16 * PITCH2,  g_whh + ((size_t)grow << 10) + koff);
        }
    };

    // group 0: xw slice [64 gate rows][64 b] + c slice + chunk 0; group 1: chunk 1
    {
#pragma unroll
        for (int it = 0; it < 4; it++) {
            int u = tid + it * 256;
            int gg = u >> 4, q = u & 15;
            const float* src = g_xw
                + ((size_t)t * G4 + (gg >> 4) * HSZ + j * 16 + (gg & 15)) * BSZ
                + mh * 64 + q * 4;
            CP16(sb + P2_XW + gg * 256 + q * 16, src);
        }
        {
            int hcr = tid >> 4, q = tid & 15;
            const float* src = g_c + (size_t)(j * 16 + hcr) * BSZ + mh * 64 + q * 4;
            CP16(sb + P2_C + hcr * 256 + q * 16, src);
        }
        load_stage(0, 0); CP_COMMIT();
        load_stage(1, 1); CP_COMMIT();
    }

    float d[2][2][4];
#pragma unroll
    for (int i = 0; i < 2; i++)
#pragma unroll
        for (int jj = 0; jj < 2; jj++)
#pragma unroll
            for (int k = 0; k < 4; k++) d[i][jj][k] = 0.0f;

    const uint32_t a_r = (uint32_t)(lane & 15) * PITCH2 + ((lane >> 4) << 4);
    const uint32_t b_r = (uint32_t)((lane & 7) + ((lane & 16) >> 1)) * PITCH2
                       + (((lane >> 3) & 1) << 4);

    int buf = 0;
    for (int c = 0; c < NCH2; c++) {
        CP_WAIT1();
        __syncthreads();
        if (c + 2 < NCH2) load_stage(c + 2, (c + 2) % 3);
        CP_COMMIT();
        const uint32_t Hb = sb + buf * P2_STG;
#pragma unroll
        for (int s2 = 0; s2 < 8; s2++) {
            uint32_t ah[2][4], al[2][4], b[4];
#pragma unroll
            for (int mt = 0; mt < 2; mt++) {
                uint32_t ro = (uint32_t)(wm * 32 + mt * 16) * PITCH2 + s2 * 32 + a_r;
                ldmx4(ah[mt], Hb + ro);
                ldmx4(al[mt], Hb + P2_ALO + ro);
            }
            ldmx4(b, Hb + P2_BB + (uint32_t)(gi * 16) * PITCH2 + s2 * 32 + b_r);
#pragma unroll
            for (int mt = 0; mt < 2; mt++)
#pragma unroll
                for (int n8 = 0; n8 < 2; n8++) {
                    mma16816(d[mt][n8], ah[mt], &b[n8 * 2]);
                    mma16816(d[mt][n8], al[mt], &b[n8 * 2]);
                }
        }
        buf = (buf == 2) ? 0 : buf + 1;
    }

    // gates to smem: sg[b_local][gate*16 + hc] (buf0 region; all warps passed
    // the chunk-7 barrier and chunk 7 reads buf1, so buf0 is dead)
    float* sg = reinterpret_cast<float*>(sm);
    const int fr = lane >> 2, fc = (lane & 3) * 2;
#pragma unroll
    for (int mt = 0; mt < 2; mt++)
#pragma unroll
        for (int n8 = 0; n8 < 2; n8++) {
            int r0 = wm * 32 + mt * 16 + fr;
            int cc = gi * 16 + n8 * 8 + fc;
            sg[(size_t)r0 * 65 + cc]           = d[mt][n8][0];
            sg[(size_t)r0 * 65 + cc + 1]       = d[mt][n8][1];
            sg[(size_t)(r0 + 8) * 65 + cc]     = d[mt][n8][2];
            sg[(size_t)(r0 + 8) * 65 + cc + 1] = d[mt][n8][3];
        }
    __syncthreads();

    // fused gate math: thread -> (b_local = tid&63, 4 hc values)
    float* sh  = reinterpret_cast<float*>(sm + P2_SH);   // [64][16]
    float* sxw = reinterpret_cast<float*>(sm + P2_XW);   // [64 gate rows][64 b]
    float* sc  = reinterpret_cast<float*>(sm + P2_C);    // [16 hc][64 b]
    {
        const int bl = tid & 63, hq = tid >> 6;
        const int bg = mh * 64 + bl;
#pragma unroll
        for (int ii = 0; ii < 4; ii++) {
            const int hc = hq * 4 + ii;
            float vi = sg[(size_t)bl * 65 + hc]      + sxw[(0 * 16 + hc) * 64 + bl];
            float vf = sg[(size_t)bl * 65 + 16 + hc] + sxw[(1 * 16 + hc) * 64 + bl];
            float vg = sg[(size_t)bl * 65 + 32 + hc] + sxw[(2 * 16 + hc) * 64 + bl];
            float vo = sg[(size_t)bl * 65 + 48 + hc] + sxw[(3 * 16 + hc) * 64 + bl];
            float ig = sigf(vi), fg = sigf(vf), og = sigf(vo);
            float ch = tanh_fast(vg);
            float cn = sc[hc * 64 + bl] * fg + ig * ch;
            g_c[(size_t)(j * 16 + hc) * BSZ + bg] = cn;
            sh[bl * 16 + hc] = og * tanh_fast(cn);
        }
    }
    __syncthreads();

    // h writeout: split to fp16 hi/lo, 16B stores
    if (tid < 128) {
        const int b = tid >> 1, half = tid & 1;
        const float* src = sh + b * 16 + half * 8;
        __align__(16) __half hi8[8], lo8[8];
#pragma unroll
        for (int i = 0; i < 8; i++) {
            float v = src[i];
            __half h = __float2half_rn(v);
            hi8[i] = h;
            lo8[i] = __float2half_rn(v - __half2float(h));
        }
        size_t dst = ((size_t)(mh * 64 + b) << 10) + j * 16 + half * 8;
        *reinterpret_cast<uint4*>(hout_hi + dst) = *reinterpret_cast<const uint4*>(hi8);
        *reinterpret_cast<uint4*>(hout_lo + dst) = *reinterpret_cast<const uint4*>(lo8);
    }
}

// ---------------------------------------------------------------------------
// Phase 3: out[b][c] = h_last . Wfc[c] + bfc[c]
// ---------------------------------------------------------------------------
__global__ __launch_bounds__(256) void fc_out(const float* __restrict__ Wfc,
                                              const float* __restrict__ bfc,
                                              float* __restrict__ out) {
    __shared__ float hs[HSZ];
    const int b = blockIdx.x;
    for (int i = threadIdx.x; i < HSZ; i += 256)
        hs[i] = __half2float(g_hhi[0][b * HSZ + i]) + __half2float(g_hlo[0][b * HSZ + i]);
    __syncthreads();

    for (int cc = threadIdx.x; cc < CSZ; cc += 256) {
        const float* wr = Wfc + (size_t)cc * HSZ;
        float acc = 0.0f;
#pragma unroll 4
        for (int k = 0; k < HSZ; k += 4) {
            float4 w = *reinterpret_cast<const float4*>(wr + k);
            acc = fmaf(hs[k + 0], w.x, acc);
            acc = fmaf(hs[k + 1], w.y, acc);
            acc = fmaf(hs[k + 2], w.z, acc);
            acc = fmaf(hs[k + 3], w.w, acc);
        }
        out[b * CSZ + cc] = acc + bfc[cc];
    }
}

// ---------------------------------------------------------------------------
// launch
// ---------------------------------------------------------------------------
extern "C" void kernel_launch(void* const* d_in, const int* in_sizes, int n_in,
                              void* d_out, int out_size) {
    const float* x   = (const float*)d_in[0];
    const float* Wxh = (const float*)d_in[1];
    const float* bxh = (const float*)d_in[2];
    const float* Whh = (const float*)d_in[3];
    const float* bhh = (const float*)d_in[4];
    const float* Wfc = (const float*)d_in[5];
    const float* bfc = (const float*)d_in[6];
    float* out = (float*)d_out;

    cudaFuncSetAttribute(gemm_xw_tc, cudaFuncAttributeMaxDynamicSharedMemorySize, P1_SMEM);
    cudaFuncSetAttribute(lstm_tc,    cudaFuncAttributeMaxDynamicSharedMemorySize, P2_SMEM);

    {
        int n4 = (BSZ * SSZ * ISZ) / 4;
        split_x<<<(n4 + 255) / 256, 256>>>(x, n4);
        n4 = (G4 * ISZ) / 4;
        round_w<<<(n4 + 255) / 256, 256>>>(Wxh, 0, n4);
        n4 = (G4 * HSZ) / 4;
        round_w<<<(n4 + 255) / 256, 256>>>(Whh, 1, n4);
    }
    init_state<<<(BSZ * HSZ + 255) / 256, 256>>>();

    dim3 g1(G4 / 128, SSZ);   // (32, 256)
    gemm_xw_tc<<<g1, 256, P1_SMEM>>>(bxh, bhh);

    dim3 g2(HSZ / 16, 2);     // (64, 2)
    for (int t = 0; t < SSZ; t++)
        lstm_tc<<<g2, 256, P2_SMEM>>>(t);

    fc_out<<<BSZ, 256>>>(Wfc, bfc, out);
}

// round 7
// speedup vs baseline: 2.3683x; 1.5114x over previous
#include <cuda_runtime.h>
#include <cuda_fp16.h>
#include <cstdint>
#include <math.h>

#define BSZ 128
#define SSZ 256
#define ISZ 1024
#define HSZ 1024
#define G4  4096
#define CSZ 1000

// ---------------------------------------------------------------------------
// Device-global scratch
// ---------------------------------------------------------------------------
__device__ float g_xw[(size_t)SSZ * G4 * BSZ];        // [s][g][b] fp32
__device__ __half g_xh[(size_t)BSZ * SSZ * ISZ];      // x rounded fp16 [b][s][k]
__device__ __half g_wxh[(size_t)G4 * ISZ];            // Wxh rounded fp16
__device__ __half g_whh[(size_t)G4 * HSZ];            // Whh rounded fp16
__device__ __half g_h[2][BSZ * HSZ];                  // h ping-pong fp16 [b][k]
__device__ float g_c[HSZ * BSZ];                      // c, [hc][b]

// ---------------------------------------------------------------------------
// PTX helpers (sm_103 baseline: ldmatrix / mma.sync / cp.async)
// ---------------------------------------------------------------------------
__device__ __forceinline__ uint32_t smem_u32(const void* p) {
    uint32_t a;
    asm("{ .reg .u64 t; cvta.to.shared.u64 t, %1; cvt.u32.u64 %0, t; }"
        : "=r"(a) : "l"(p));
    return a;
}

#define CP16(s, g) \
    asm volatile("cp.async.cg.shared.global [%0], [%1], 16;" :: "r"(s), "l"(g))
#define CP_COMMIT() asm volatile("cp.async.commit_group;" ::: "memory")
#define CP_WAIT1()  asm volatile("cp.async.wait_group 1;" ::: "memory")
#define CP_WAIT2()  asm volatile("cp.async.wait_group 2;" ::: "memory")

__device__ __forceinline__ void ldmx4(uint32_t* r, uint32_t addr) {
    asm volatile("ldmatrix.sync.aligned.m8n8.x4.shared.b16 {%0,%1,%2,%3}, [%4];"
        : "=r"(r[0]), "=r"(r[1]), "=r"(r[2]), "=r"(r[3]) : "r"(addr));
}

__device__ __forceinline__ void mma16816(float* d, const uint32_t* a, const uint32_t* b) {
    asm volatile(
        "mma.sync.aligned.m16n8k16.row.col.f32.f16.f16.f32 "
        "{%0,%1,%2,%3}, {%4,%5,%6,%7}, {%8,%9}, {%0,%1,%2,%3};"
        : "+f"(d[0]), "+f"(d[1]), "+f"(d[2]), "+f"(d[3])
        : "r"(a[0]), "r"(a[1]), "r"(a[2]), "r"(a[3]), "r"(b[0]), "r"(b[1]));
}

__device__ __forceinline__ float sigf(float x) { return 1.0f / (1.0f + __expf(-x)); }
__device__ __forceinline__ float tanh_fast(float x) {
    float e = __expf(fminf(fmaxf(2.0f * x, -30.0f), 30.0f));
    return __fdividef(e - 1.0f, e + 1.0f);
}

// ---------------------------------------------------------------------------
// round fp32 -> fp16
// ---------------------------------------------------------------------------
__global__ void round_h16(const float* __restrict__ src, int sel, int n4) {
    __half* dst = (sel == 0) ? g_xh : (sel == 1) ? g_wxh : g_whh;
    int i = blockIdx.x * blockDim.x + threadIdx.x;
    if (i >= n4) return;
    float4 v = reinterpret_cast<const float4*>(src)[i];
    __half2 a, b;
    a.x = __float2half_rn(v.x); a.y = __float2half_rn(v.y);
    b.x = __float2half_rn(v.z); b.y = __float2half_rn(v.w);
    reinterpret_cast<__half2*>(dst)[2 * i]     = a;
    reinterpret_cast<__half2*>(dst)[2 * i + 1] = b;
}

__global__ void init_state() {
    int i = blockIdx.x * blockDim.x + threadIdx.x;
    if (i < BSZ * HSZ) {
        g_h[0][i] = __float2half(0.0f);
        g_c[i] = 0.0f;
    }
}

// ---------------------------------------------------------------------------
// Phase 1: xw[s][g][b], M=128 (batch), N=128 gates/CTA, K=1024, 16 chunks.
// 3 smem buffers, 2 outstanding cp.async groups, 1 sync per chunk.
// ---------------------------------------------------------------------------
#define PITCH     144
#define P1_STG    36864
#define P1_BOFF   18432
#define P1_BIAS   110592
#define P1_SMEM   111104
#define NCHUNK    16

__global__ __launch_bounds__(256, 1) void gemm_xw_tc(const float* __restrict__ bxh,
                                                     const float* __restrict__ bhh) {
    extern __shared__ char sm[];
    const uint32_t sb = smem_u32(sm);
    const int tid = threadIdx.x;
    const int wid = tid >> 5, lane = tid & 31;
    const int s  = blockIdx.y;
    const int n0 = blockIdx.x * 128;

    float* sbias = reinterpret_cast<float*>(sm + P1_BIAS);
    if (tid < 128) sbias[tid] = bxh[n0 + tid] + bhh[n0 + tid];

    const int wm = wid >> 2, wn = wid & 3;
    const int lrow = tid >> 3, lq = tid & 7;

    auto load_stage = [&](int c, int buf) {
        const int koff = c * 64 + lq * 8;
        uint32_t Ab = sb + buf * P1_STG + lrow * PITCH + lq * 16;
        uint32_t Bb = Ab + P1_BOFF;
#pragma unroll
        for (int i = 0; i < 4; i++) {
            int row = lrow + i * 32;
            CP16(Ab + i * 32 * PITCH, g_xh + (((size_t)((row << 8) + s)) << 10) + koff);
            CP16(Bb + i * 32 * PITCH, g_wxh + (((size_t)(n0 + row)) << 10) + koff);
        }
    };

    load_stage(0, 0); CP_COMMIT();
    load_stage(1, 1); CP_COMMIT();

    float d[4][4][4];
#pragma unroll
    for (int i = 0; i < 4; i++)
#pragma unroll
        for (int j = 0; j < 4; j++)
#pragma unroll
            for (int k = 0; k < 4; k++) d[i][j][k] = 0.0f;

    const uint32_t a_r = (uint32_t)(lane & 15) * PITCH + ((lane >> 4) << 4);
    const uint32_t b_r = (uint32_t)((lane & 7) + ((lane & 16) >> 1)) * PITCH
                       + (((lane >> 3) & 1) << 4);

    int buf = 0;
    for (int c = 0; c < NCHUNK; c++) {
        CP_WAIT1();
        __syncthreads();
        if (c + 2 < NCHUNK) load_stage(c + 2, (c + 2) % 3);
        CP_COMMIT();
        const uint32_t Ab = sb + buf * P1_STG;
        const uint32_t Bb = Ab + P1_BOFF;
#pragma unroll
        for (int s2 = 0; s2 < 4; s2++) {
            uint32_t a[4][4], b[2][4];
#pragma unroll
            for (int mt = 0; mt < 4; mt++)
                ldmx4(a[mt], Ab + (uint32_t)(wm * 64 + mt * 16) * PITCH + s2 * 32 + a_r);
#pragma unroll
            for (int nt = 0; nt < 2; nt++)
                ldmx4(b[nt], Bb + (uint32_t)(wn * 32 + nt * 16) * PITCH + s2 * 32 + b_r);
#pragma unroll
            for (int mt = 0; mt < 4; mt++)
#pragma unroll
                for (int n8 = 0; n8 < 4; n8++)
                    mma16816(d[mt][n8], a[mt], &b[n8 >> 1][(n8 & 1) * 2]);
        }
        buf = (buf == 2) ? 0 : buf + 1;
    }

    // epilogue: transpose through smem, coalesced writeout with bias
    __syncthreads();
    float* tile = reinterpret_cast<float*>(sm);  // [g:128][pitch 132]
    const int fr = lane >> 2, fc = (lane & 3) * 2;
#pragma unroll
    for (int mt = 0; mt < 4; mt++)
#pragma unroll
        for (int n8 = 0; n8 < 4; n8++) {
            int r0 = wm * 64 + mt * 16 + fr;
            int cc = wn * 32 + n8 * 8 + fc;
            tile[(size_t)cc * 132 + r0]           = d[mt][n8][0];
            tile[(size_t)(cc + 1) * 132 + r0]     = d[mt][n8][1];
            tile[(size_t)cc * 132 + r0 + 8]       = d[mt][n8][2];
            tile[(size_t)(cc + 1) * 132 + r0 + 8] = d[mt][n8][3];
        }
    __syncthreads();
#pragma unroll
    for (int it = 0; it < 16; it++) {
        int u = tid + it * 256;
        int g = u >> 5, q = u & 31;
        float4 v = *reinterpret_cast<const float4*>(tile + (size_t)g * 132 + q * 4);
        float bi = sbias[g];
        v.x += bi; v.y += bi; v.z += bi; v.w += bi;
        *reinterpret_cast<float4*>(g_xw + ((size_t)s * G4 + n0 + g) * BSZ + q * 4) = v;
    }
}

// ---------------------------------------------------------------------------
// Phase 2: one LSTM step. Grid (64, 2): j = 16-hidden-col group, mh = batch half.
// CTA: M=64 (batch) x N=64 (4 gates x 16 hidden), K=1024 in 8 chunks of 128.
// 4 smem buffers, 3 outstanding cp.async groups, 1 sync per chunk.
// smem: 4 stages of 34816 | sxw @139264 (+16384) | sc @155648 (+4096) = 159744
// epilogue overlays: sg f32[64][65] @0, sh f32[64][16] @16640 (in buf0; safe)
// ---------------------------------------------------------------------------
#define PITCH2   272
#define P2_BB    17408
#define P2_STG   34816
#define P2_XW    139264
#define P2_C     155648
#define P2_SH    16640
#define P2_SMEM  159744
#define NCH2     8

__global__ __launch_bounds__(256, 1) void lstm_tc(int t) {
    extern __shared__ char sm[];
    const uint32_t sb = smem_u32(sm);
    const int tid = threadIdx.x;
    const int wid = tid >> 5, lane = tid & 31;
    const int j = blockIdx.x;      // hidden col group (16)
    const int mh = blockIdx.y;     // batch half

    const __half* __restrict__ hin = g_h[t & 1];
    __half* __restrict__ hout = g_h[(t + 1) & 1];

    const int wm = wid >> 2, gi = wid & 3;
    const int lrow = tid >> 4, lq = tid & 15;   // 16 rows x 16 quads (256B row)

    auto load_stage = [&](int c, int buf) {
        const int koff = c * 128 + lq * 8;
        uint32_t Sb = sb + buf * P2_STG + lrow * PITCH2 + lq * 16;
#pragma unroll
        for (int i = 0; i < 4; i++) {
            int row = lrow + i * 16;
            CP16(Sb + i * 16 * PITCH2, hin + ((size_t)(mh * 64 + row) << 10) + koff);
            int grow = (row >> 4) * HSZ + j * 16 + (row & 15);
            CP16(Sb + P2_BB + i * 16 * PITCH2, g_whh + ((size_t)grow << 10) + koff);
        }
    };

    // group 0: xw slice [64 gate rows][64 b] + c slice + chunk 0; then 1, 2
    {
#pragma unroll
        for (int it = 0; it < 4; it++) {
            int u = tid + it * 256;
            int gg = u >> 4, q = u & 15;
            const float* src = g_xw
                + ((size_t)t * G4 + (gg >> 4) * HSZ + j * 16 + (gg & 15)) * BSZ
                + mh * 64 + q * 4;
            CP16(sb + P2_XW + gg * 256 + q * 16, src);
        }
        {
            int hcr = tid >> 4, q = tid & 15;
            const float* src = g_c + (size_t)(j * 16 + hcr) * BSZ + mh * 64 + q * 4;
            CP16(sb + P2_C + hcr * 256 + q * 16, src);
        }
        load_stage(0, 0); CP_COMMIT();
        load_stage(1, 1); CP_COMMIT();
        load_stage(2, 2); CP_COMMIT();
    }

    float d[2][2][4];
#pragma unroll
    for (int i = 0; i < 2; i++)
#pragma unroll
        for (int jj = 0; jj < 2; jj++)
#pragma unroll
            for (int k = 0; k < 4; k++) d[i][jj][k] = 0.0f;

    const uint32_t a_r = (uint32_t)(lane & 15) * PITCH2 + ((lane >> 4) << 4);
    const uint32_t b_r = (uint32_t)((lane & 7) + ((lane & 16) >> 1)) * PITCH2
                       + (((lane >> 3) & 1) << 4);

    int buf = 0;
    for (int c = 0; c < NCH2; c++) {
        CP_WAIT2();
        __syncthreads();
        if (c + 3 < NCH2) load_stage(c + 3, (c + 3) & 3);
        CP_COMMIT();
        const uint32_t Hb = sb + buf * P2_STG;
#pragma unroll
        for (int s2 = 0; s2 < 8; s2++) {
            uint32_t a[2][4], b[4];
#pragma unroll
            for (int mt = 0; mt < 2; mt++)
                ldmx4(a[mt], Hb + (uint32_t)(wm * 32 + mt * 16) * PITCH2 + s2 * 32 + a_r);
            ldmx4(b, Hb + P2_BB + (uint32_t)(gi * 16) * PITCH2 + s2 * 32 + b_r);
#pragma unroll
            for (int mt = 0; mt < 2; mt++)
#pragma unroll
                for (int n8 = 0; n8 < 2; n8++)
                    mma16816(d[mt][n8], a[mt], &b[n8 * 2]);
        }
        buf = (buf + 1) & 3;
    }

    // gates to smem: sg[b_local][gate*16 + hc] (buf0/1 region; chunk 7 reads
    // buf3 and every warp passed the c=7 barrier, so buf0/1 are dead)
    float* sg = reinterpret_cast<float*>(sm);
    const int fr = lane >> 2, fc = (lane & 3) * 2;
#pragma unroll
    for (int mt = 0; mt < 2; mt++)
#pragma unroll
        for (int n8 = 0; n8 < 2; n8++) {
            int r0 = wm * 32 + mt * 16 + fr;
            int cc = gi * 16 + n8 * 8 + fc;
            sg[(size_t)r0 * 65 + cc]           = d[mt][n8][0];
            sg[(size_t)r0 * 65 + cc + 1]       = d[mt][n8][1];
            sg[(size_t)(r0 + 8) * 65 + cc]     = d[mt][n8][2];
            sg[(size_t)(r0 + 8) * 65 + cc + 1] = d[mt][n8][3];
        }
    __syncthreads();

    // fused gate math: thread -> (b_local = tid&63, 4 hc values)
    float* sh  = reinterpret_cast<float*>(sm + P2_SH);   // [64][16]
    float* sxw = reinterpret_cast<float*>(sm + P2_XW);   // [64 gate rows][64 b]
    float* sc  = reinterpret_cast<float*>(sm + P2_C);    // [16 hc][64 b]
    {
        const int bl = tid & 63, hq = tid >> 6;
        const int bg = mh * 64 + bl;
#pragma unroll
        for (int ii = 0; ii < 4; ii++) {
            const int hc = hq * 4 + ii;
            float vi = sg[(size_t)bl * 65 + hc]      + sxw[(0 * 16 + hc) * 64 + bl];
            float vf = sg[(size_t)bl * 65 + 16 + hc] + sxw[(1 * 16 + hc) * 64 + bl];
            float vg = sg[(size_t)bl * 65 + 32 + hc] + sxw[(2 * 16 + hc) * 64 + bl];
            float vo = sg[(size_t)bl * 65 + 48 + hc] + sxw[(3 * 16 + hc) * 64 + bl];
            float ig = sigf(vi), fg = sigf(vf), og = sigf(vo);
            float ch = tanh_fast(vg);
            float cn = sc[hc * 64 + bl] * fg + ig * ch;
            g_c[(size_t)(j * 16 + hc) * BSZ + bg] = cn;
            sh[bl * 16 + hc] = og * tanh_fast(cn);
        }
    }
    __syncthreads();

    // h writeout: fp16, 16B stores (64 rows x 16 cols = 128 stores of 8 halves)
    if (tid < 128) {
        const int b = tid >> 1, half = tid & 1;
        const float* src = sh + b * 16 + half * 8;
        __align__(16) __half h8[8];
#pragma unroll
        for (int i = 0; i < 8; i++) h8[i] = __float2half_rn(src[i]);
        size_t dst = ((size_t)(mh * 64 + b) << 10) + j * 16 + half * 8;
        *reinterpret_cast<uint4*>(hout + dst) = *reinterpret_cast<const uint4*>(h8);
    }
}

// ---------------------------------------------------------------------------
// Phase 3: out[b][c] = h_last . Wfc[c] + bfc[c]
// ---------------------------------------------------------------------------
__global__ __launch_bounds__(256) void fc_out(const float* __restrict__ Wfc,
                                              const float* __restrict__ bfc,
                                              float* __restrict__ out) {
    __shared__ float hs[HSZ];
    const int b = blockIdx.x;
    for (int i = threadIdx.x; i < HSZ; i += 256)
        hs[i] = __half2float(g_h[0][b * HSZ + i]);
    __syncthreads();

    for (int cc = threadIdx.x; cc < CSZ; cc += 256) {
        const float* wr = Wfc + (size_t)cc * HSZ;
        float acc = 0.0f;
#pragma unroll 4
        for (int k = 0; k < HSZ; k += 4) {
            float4 w = *reinterpret_cast<const float4*>(wr + k);
            acc = fmaf(hs[k + 0], w.x, acc);
            acc = fmaf(hs[k + 1], w.y, acc);
            acc = fmaf(hs[k + 2], w.z, acc);
            acc = fmaf(hs[k + 3], w.w, acc);
        }
        out[b * CSZ + cc] = acc + bfc[cc];
    }
}

// ---------------------------------------------------------------------------
// launch
// ---------------------------------------------------------------------------
extern "C" void kernel_launch(void* const* d_in, const int* in_sizes, int n_in,
                              void* d_out, int out_size) {
    const float* x   = (const float*)d_in[0];
    const float* Wxh = (const float*)d_in[1];
    const float* bxh = (const float*)d_in[2];
    const float* Whh = (const float*)d_in[3];
    const float* bhh = (const float*)d_in[4];
    const float* Wfc = (const float*)d_in[5];
    const float* bfc = (const float*)d_in[6];
    float* out = (float*)d_out;

    cudaFuncSetAttribute(gemm_xw_tc, cudaFuncAttributeMaxDynamicSharedMemorySize, P1_SMEM);
    cudaFuncSetAttribute(lstm_tc,    cudaFuncAttributeMaxDynamicSharedMemorySize, P2_SMEM);

    {
        int n4 = (BSZ * SSZ * ISZ) / 4;
        round_h16<<<(n4 + 255) / 256, 256>>>(x, 0, n4);
        n4 = (G4 * ISZ) / 4;
        round_h16<<<(n4 + 255) / 256, 256>>>(Wxh, 1, n4);
        n4 = (G4 * HSZ) / 4;
        round_h16<<<(n4 + 255) / 256, 256>>>(Whh, 2, n4);
    }
    init_state<<<(BSZ * HSZ + 255) / 256, 256>>>();

    dim3 g1(G4 / 128, SSZ);   // (32, 256)
    gemm_xw_tc<<<g1, 256, P1_SMEM>>>(bxh, bhh);

    dim3 g2(HSZ / 16, 2);     // (64, 2)
    for (int t = 0; t < SSZ; t++)
        lstm_tc<<<g2, 256, P2_SMEM>>>(t);

    fc_out<<<BSZ, 256>>>(Wfc, bfc, out);
}

// round 8
// speedup vs baseline: 2.5530x; 1.0780x over previous
#include <cuda_runtime.h>
#include <cuda_fp16.h>
#include <cstdint>
#include <math.h>

#define BSZ 128
#define SSZ 256
#define ISZ 1024
#define HSZ 1024
#define G4  4096
#define CSZ 1000

#define GRID2 128

// ---------------------------------------------------------------------------
// Device-global scratch
// ---------------------------------------------------------------------------
__device__ float g_xw[(size_t)SSZ * G4 * BSZ];        // [s][g][b] fp32
__device__ __half g_xh[(size_t)BSZ * SSZ * ISZ];      // x rounded fp16 [b][s][k]
__device__ __half g_wxh[(size_t)G4 * ISZ];            // Wxh rounded fp16
__device__ __half g_whh[(size_t)G4 * HSZ];            // Whh rounded fp16
__device__ __half g_h[2][BSZ * HSZ];                  // h ping-pong fp16 [b][k]
__device__ unsigned g_bar_count;                      // zero-init (bss)
__device__ unsigned g_bar_gen;

// ---------------------------------------------------------------------------
// PTX helpers
// ---------------------------------------------------------------------------
__device__ __forceinline__ uint32_t smem_u32(const void* p) {
    uint32_t a;
    asm("{ .reg .u64 t; cvta.to.shared.u64 t, %1; cvt.u32.u64 %0, t; }"
        : "=r"(a) : "l"(p));
    return a;
}

#define CP16(s, g) \
    asm volatile("cp.async.cg.shared.global [%0], [%1], 16;" :: "r"(s), "l"(g))
#define CP_COMMIT() asm volatile("cp.async.commit_group;" ::: "memory")
#define CP_WAIT1()  asm volatile("cp.async.wait_group 1;" ::: "memory")
#define CP_WAIT0()  asm volatile("cp.async.wait_group 0;" ::: "memory")

__device__ __forceinline__ void ldmx4(uint32_t* r, uint32_t addr) {
    asm volatile("ldmatrix.sync.aligned.m8n8.x4.shared.b16 {%0,%1,%2,%3}, [%4];"
        : "=r"(r[0]), "=r"(r[1]), "=r"(r[2]), "=r"(r[3]) : "r"(addr));
}

__device__ __forceinline__ void mma16816(float* d, const uint32_t* a, const uint32_t* b) {
    asm volatile(
        "mma.sync.aligned.m16n8k16.row.col.f32.f16.f16.f32 "
        "{%0,%1,%2,%3}, {%4,%5,%6,%7}, {%8,%9}, {%0,%1,%2,%3};"
        : "+f"(d[0]), "+f"(d[1]), "+f"(d[2]), "+f"(d[3])
        : "r"(a[0]), "r"(a[1]), "r"(a[2]), "r"(a[3]), "r"(b[0]), "r"(b[1]));
}

__device__ __forceinline__ float sigf(float x) { return 1.0f / (1.0f + __expf(-x)); }
__device__ __forceinline__ float tanh_fast(float x) {
    float e = __expf(fminf(fmaxf(2.0f * x, -30.0f), 30.0f));
    return __fdividef(e - 1.0f, e + 1.0f);
}

// ---------------------------------------------------------------------------
// round fp32 -> fp16
// ---------------------------------------------------------------------------
__global__ void round_h16(const float* __restrict__ src, int sel, int n4) {
    __half* dst = (sel == 0) ? g_xh : (sel == 1) ? g_wxh : g_whh;
    int i = blockIdx.x * blockDim.x + threadIdx.x;
    if (i >= n4) return;
    float4 v = reinterpret_cast<const float4*>(src)[i];
    __half2 a, b;
    a.x = __float2half_rn(v.x); a.y = __float2half_rn(v.y);
    b.x = __float2half_rn(v.z); b.y = __float2half_rn(v.w);
    reinterpret_cast<__half2*>(dst)[2 * i]     = a;
    reinterpret_cast<__half2*>(dst)[2 * i + 1] = b;
}

__global__ void init_state() {
    int i = blockIdx.x * blockDim.x + threadIdx.x;
    if (i < BSZ * HSZ) g_h[0][i] = __float2half(0.0f);
}

// ---------------------------------------------------------------------------
// Phase 1: xw[s][g][b], M=128 (batch), N=128 gates/CTA, K=1024, 16 chunks.
// (unchanged from R7)
// ---------------------------------------------------------------------------
#define PITCH     144
#define P1_STG    36864
#define P1_BOFF   18432
#define P1_BIAS   110592
#define P1_SMEM   111104
#define NCHUNK    16

__global__ __launch_bounds__(256, 1) void gemm_xw_tc(const float* __restrict__ bxh,
                                                     const float* __restrict__ bhh) {
    extern __shared__ char sm[];
    const uint32_t sb = smem_u32(sm);
    const int tid = threadIdx.x;
    const int wid = tid >> 5, lane = tid & 31;
    const int s  = blockIdx.y;
    const int n0 = blockIdx.x * 128;

    float* sbias = reinterpret_cast<float*>(sm + P1_BIAS);
    if (tid < 128) sbias[tid] = bxh[n0 + tid] + bhh[n0 + tid];

    const int wm = wid >> 2, wn = wid & 3;
    const int lrow = tid >> 3, lq = tid & 7;

    auto load_stage = [&](int c, int buf) {
        const int koff = c * 64 + lq * 8;
        uint32_t Ab = sb + buf * P1_STG + lrow * PITCH + lq * 16;
        uint32_t Bb = Ab + P1_BOFF;
#pragma unroll
        for (int i = 0; i < 4; i++) {
            int row = lrow + i * 32;
            CP16(Ab + i * 32 * PITCH, g_xh + (((size_t)((row << 8) + s)) << 10) + koff);
            CP16(Bb + i * 32 * PITCH, g_wxh + (((size_t)(n0 + row)) << 10) + koff);
        }
    };

    load_stage(0, 0); CP_COMMIT();
    load_stage(1, 1); CP_COMMIT();

    float d[4][4][4];
#pragma unroll
    for (int i = 0; i < 4; i++)
#pragma unroll
        for (int j = 0; j < 4; j++)
#pragma unroll
            for (int k = 0; k < 4; k++) d[i][j][k] = 0.0f;

    const uint32_t a_r = (uint32_t)(lane & 15) * PITCH + ((lane >> 4) << 4);
    const uint32_t b_r = (uint32_t)((lane & 7) + ((lane & 16) >> 1)) * PITCH
                       + (((lane >> 3) & 1) << 4);

    int buf = 0;
    for (int c = 0; c < NCHUNK; c++) {
        CP_WAIT1();
        __syncthreads();
        if (c + 2 < NCHUNK) load_stage(c + 2, (c + 2) % 3);
        CP_COMMIT();
        const uint32_t Ab = sb + buf * P1_STG;
        const uint32_t Bb = Ab + P1_BOFF;
#pragma unroll
        for (int s2 = 0; s2 < 4; s2++) {
            uint32_t a[4][4], b[2][4];
#pragma unroll
            for (int mt = 0; mt < 4; mt++)
                ldmx4(a[mt], Ab + (uint32_t)(wm * 64 + mt * 16) * PITCH + s2 * 32 + a_r);
#pragma unroll
            for (int nt = 0; nt < 2; nt++)
                ldmx4(b[nt], Bb + (uint32_t)(wn * 32 + nt * 16) * PITCH + s2 * 32 + b_r);
#pragma unroll
            for (int mt = 0; mt < 4; mt++)
#pragma unroll
                for (int n8 = 0; n8 < 4; n8++)
                    mma16816(d[mt][n8], a[mt], &b[n8 >> 1][(n8 & 1) * 2]);
        }
        buf = (buf == 2) ? 0 : buf + 1;
    }

    __syncthreads();
    float* tile = reinterpret_cast<float*>(sm);  // [g:128][pitch 132]
    const int fr = lane >> 2, fc = (lane & 3) * 2;
#pragma unroll
    for (int mt = 0; mt < 4; mt++)
#pragma unroll
        for (int n8 = 0; n8 < 4; n8++) {
            int r0 = wm * 64 + mt * 16 + fr;
            int cc = wn * 32 + n8 * 8 + fc;
            tile[(size_t)cc * 132 + r0]           = d[mt][n8][0];
            tile[(size_t)(cc + 1) * 132 + r0]     = d[mt][n8][1];
            tile[(size_t)cc * 132 + r0 + 8]       = d[mt][n8][2];
            tile[(size_t)(cc + 1) * 132 + r0 + 8] = d[mt][n8][3];
        }
    __syncthreads();
#pragma unroll
    for (int it = 0; it < 16; it++) {
        int u = tid + it * 256;
        int g = u >> 5, q = u & 31;
        float4 v = *reinterpret_cast<const float4*>(tile + (size_t)g * 132 + q * 4);
        float bi = sbias[g];
        v.x += bi; v.y += bi; v.z += bi; v.w += bi;
        *reinterpret_cast<float4*>(g_xw + ((size_t)s * G4 + n0 + g) * BSZ + q * 4) = v;
    }
}

// ---------------------------------------------------------------------------
// Phase 2: PERSISTENT recurrence. 128 CTAs: j = bid>>1 (16 hidden cols),
// mh = bid&1 (batch half). Per step: M=64 x N=64 x K=1024 (8 chunks of 128).
// Whh slice (8 chunks x 64rows x 272B = 136KB) resident in smem for all steps.
// A (h): 3 stages, WAIT1, 2 outstanding. xw double-buffered, t+1 prefetched
// during step t mainloop. c in registers. Grid barrier between steps.
// smem: B 0..139264 | A 139264 (3x17408) | XW 191488 (2x16384) | = 224256
// epilogue overlays: sg f32[64][65] @A+0 (buf0), sh f32[64][16] @A+34816 (buf2)
// ---------------------------------------------------------------------------
#define PITCH2   272
#define PB_STG   17408
#define PA_OFF   139264
#define PXW_OFF  191488
#define P2_SMEM  224256
#define NCH2     8

__global__ __launch_bounds__(256, 1) void lstm_persist() {
    extern __shared__ char sm[];
    const uint32_t sb = smem_u32(sm);
    const int tid = threadIdx.x;
    const int wid = tid >> 5, lane = tid & 31;
    const int bid = blockIdx.x;
    const int j  = bid >> 1;
    const int mh = bid & 1;

    const int wm = wid >> 2, gi = wid & 3;
    const int lrow = tid >> 4, lq = tid & 15;   // 16 rows x 16 quads

    const uint32_t a_r = (uint32_t)(lane & 15) * PITCH2 + ((lane >> 4) << 4);
    const uint32_t b_r = (uint32_t)((lane & 7) + ((lane & 16) >> 1)) * PITCH2
                       + (((lane >> 3) & 1) << 4);

    auto xw_load = [&](int t, int slot) {
#pragma unroll
        for (int it = 0; it < 4; it++) {
            int u = tid + it * 256;
            int gg = u >> 4, q = u & 15;
            const float* src = g_xw
                + ((size_t)t * G4 + (gg >> 4) * HSZ + j * 16 + (gg & 15)) * BSZ
                + mh * 64 + q * 4;
            CP16(sb + PXW_OFF + slot * 16384 + gg * 256 + q * 16, src);
        }
    };

    // ---- one-time: resident Whh slice (8 chunks) + xw(0) ----
    for (int c = 0; c < NCH2; c++) {
        const int koff = c * 128 + lq * 8;
        uint32_t Sb = sb + c * PB_STG + lrow * PITCH2 + lq * 16;
#pragma unroll
        for (int i = 0; i < 4; i++) {
            int row = lrow + i * 16;
            int grow = (row >> 4) * HSZ + j * 16 + (row & 15);
            CP16(Sb + i * 16 * PITCH2, g_whh + ((size_t)grow << 10) + koff);
        }
    }
    xw_load(0, 0);
    CP_COMMIT();
    CP_WAIT0();
    __syncthreads();

    // barrier base generation (robust across graph replays)
    __shared__ unsigned s_gen;
    if (tid == 0) s_gen = *(volatile unsigned*)&g_bar_gen;
    __syncthreads();
    unsigned gen = s_gen;

    // cell state in registers: thread owns (bl, hq) -> 4 hidden cols
    const int bl = tid & 63, hq = tid >> 6;
    float cre[4] = {0.0f, 0.0f, 0.0f, 0.0f};

    float* sg = reinterpret_cast<float*>(sm + PA_OFF);                 // buf0
    float* sh = reinterpret_cast<float*>(sm + PA_OFF + 2 * PB_STG);    // buf2

    for (int t = 0; t < SSZ; t++) {
        if (t > 0) {
            // grid barrier: h(t) must be globally visible
            __syncthreads();
            if (tid == 0) {
                __threadfence();
                unsigned arrived = atomicAdd(&g_bar_count, 1u);
                if (arrived == GRID2 - 1) {
                    *(volatile unsigned*)&g_bar_count = 0;
                    __threadfence();
                    atomicAdd(&g_bar_gen, 1u);
                } else {
                    while (*(volatile unsigned*)&g_bar_gen == gen) { __nanosleep(32); }
                    __threadfence();
                }
            }
            __syncthreads();
            gen++;
        }

        const __half* __restrict__ hin = g_h[t & 1];
        __half* __restrict__ hout = g_h[(t + 1) & 1];

        auto loadA = [&](int c, int buf) {
            const int koff = c * 128 + lq * 8;
            uint32_t Sb = sb + PA_OFF + buf * PB_STG + lrow * PITCH2 + lq * 16;
#pragma unroll
            for (int i = 0; i < 4; i++) {
                int row = lrow + i * 16;
                CP16(Sb + i * 16 * PITCH2, hin + ((size_t)(mh * 64 + row) << 10) + koff);
            }
        };

        loadA(0, 0); CP_COMMIT();
        loadA(1, 1); CP_COMMIT();

        float d[2][2][4];
#pragma unroll
        for (int i = 0; i < 2; i++)
#pragma unroll
            for (int jj = 0; jj < 2; jj++)
#pragma unroll
                for (int k = 0; k < 4; k++) d[i][jj][k] = 0.0f;

        int buf = 0;
        for (int c = 0; c < NCH2; c++) {
            CP_WAIT1();
            __syncthreads();
            if (c + 2 < NCH2) loadA(c + 2, (c + 2) % 3);
            if (c == 0 && t + 1 < SSZ) xw_load(t + 1, (t + 1) & 1);
            CP_COMMIT();
            const uint32_t Hb = sb + PA_OFF + buf * PB_STG;
            const uint32_t Bb = sb + c * PB_STG;     // resident Whh chunk c
#pragma unroll
            for (int s2 = 0; s2 < 8; s2++) {
                uint32_t a[2][4], b[4];
#pragma unroll
                for (int mt = 0; mt < 2; mt++)
                    ldmx4(a[mt], Hb + (uint32_t)(wm * 32 + mt * 16) * PITCH2 + s2 * 32 + a_r);
                ldmx4(b, Bb + (uint32_t)(gi * 16) * PITCH2 + s2 * 32 + b_r);
#pragma unroll
                for (int mt = 0; mt < 2; mt++)
#pragma unroll
                    for (int n8 = 0; n8 < 2; n8++)
                        mma16816(d[mt][n8], a[mt], &b[n8 * 2]);
            }
            buf = (buf == 2) ? 0 : buf + 1;
        }

        // gates to smem: sg[b_local][gate*16 + hc] in A-buf0 (max skew = 1
        // chunk: every warp passed the c=7 top barrier, chunk 7 reads buf1)
        const int fr = lane >> 2, fc = (lane & 3) * 2;
#pragma unroll
        for (int mt = 0; mt < 2; mt++)
#pragma unroll
            for (int n8 = 0; n8 < 2; n8++) {
                int r0 = wm * 32 + mt * 16 + fr;
                int cc = gi * 16 + n8 * 8 + fc;
                sg[(size_t)r0 * 65 + cc]           = d[mt][n8][0];
                sg[(size_t)r0 * 65 + cc + 1]       = d[mt][n8][1];
                sg[(size_t)(r0 + 8) * 65 + cc]     = d[mt][n8][2];
                sg[(size_t)(r0 + 8) * 65 + cc + 1] = d[mt][n8][3];
            }
        __syncthreads();

        // fused gate math; c in registers
        const float* sxw = reinterpret_cast<const float*>(sm + PXW_OFF + (t & 1) * 16384);
#pragma unroll
        for (int ii = 0; ii < 4; ii++) {
            const int hc = hq * 4 + ii;
            float vi = sg[(size_t)bl * 65 + hc]      + sxw[(0 * 16 + hc) * 64 + bl];
            float vf = sg[(size_t)bl * 65 + 16 + hc] + sxw[(1 * 16 + hc) * 64 + bl];
            float vg = sg[(size_t)bl * 65 + 32 + hc] + sxw[(2 * 16 + hc) * 64 + bl];
            float vo = sg[(size_t)bl * 65 + 48 + hc] + sxw[(3 * 16 + hc) * 64 + bl];
            float ig = sigf(vi), fg = sigf(vf), og = sigf(vo);
            float ch = tanh_fast(vg);
            float cn = cre[ii] * fg + ig * ch;
            cre[ii] = cn;
            sh[bl * 16 + hc] = og * tanh_fast(cn);
        }
        __syncthreads();

        // h writeout: fp16, 16B stores
        if (tid < 128) {
            const int b = tid >> 1, half = tid & 1;
            const float* src = sh + b * 16 + half * 8;
            __align__(16) __half h8[8];
#pragma unroll
            for (int i = 0; i < 8; i++) h8[i] = __float2half_rn(src[i]);
            size_t dst = ((size_t)(mh * 64 + b) << 10) + j * 16 + half * 8;
            *reinterpret_cast<uint4*>(hout + dst) = *reinterpret_cast<const uint4*>(h8);
        }
    }
}

// ---------------------------------------------------------------------------
// Phase 3: out[b][c] = h_last . Wfc[c] + bfc[c]
// ---------------------------------------------------------------------------
__global__ __launch_bounds__(256) void fc_out(const float* __restrict__ Wfc,
                                              const float* __restrict__ bfc,
                                              float* __restrict__ out) {
    __shared__ float hs[HSZ];
    const int b = blockIdx.x;
    for (int i = threadIdx.x; i < HSZ; i += 256)
        hs[i] = __half2float(g_h[0][b * HSZ + i]);
    __syncthreads();

    for (int cc = threadIdx.x; cc < CSZ; cc += 256) {
        const float* wr = Wfc + (size_t)cc * HSZ;
        float acc = 0.0f;
#pragma unroll 4
        for (int k = 0; k < HSZ; k += 4) {
            float4 w = *reinterpret_cast<const float4*>(wr + k);
            acc = fmaf(hs[k + 0], w.x, acc);
            acc = fmaf(hs[k + 1], w.y, acc);
            acc = fmaf(hs[k + 2], w.z, acc);
            acc = fmaf(hs[k + 3], w.w, acc);
        }
        out[b * CSZ + cc] = acc + bfc[cc];
    }
}

// ---------------------------------------------------------------------------
// launch
// ---------------------------------------------------------------------------
extern "C" void kernel_launch(void* const* d_in, const int* in_sizes, int n_in,
                              void* d_out, int out_size) {
    const float* x   = (const float*)d_in[0];
    const float* Wxh = (const float*)d_in[1];
    const float* bxh = (const float*)d_in[2];
    const float* Whh = (const float*)d_in[3];
    const float* bhh = (const float*)d_in[4];
    const float* Wfc = (const float*)d_in[5];
    const float* bfc = (const float*)d_in[6];
    float* out = (float*)d_out;

    cudaFuncSetAttribute(gemm_xw_tc,   cudaFuncAttributeMaxDynamicSharedMemorySize, P1_SMEM);
    cudaFuncSetAttribute(lstm_persist, cudaFuncAttributeMaxDynamicSharedMemorySize, P2_SMEM);

    {
        int n4 = (BSZ * SSZ * ISZ) / 4;
        round_h16<<<(n4 + 255) / 256, 256>>>(x, 0, n4);
        n4 = (G4 * ISZ) / 4;
        round_h16<<<(n4 + 255) / 256, 256>>>(Wxh, 1, n4);
        n4 = (G4 * HSZ) / 4;
        round_h16<<<(n4 + 255) / 256, 256>>>(Whh, 2, n4);
    }
    init_state<<<(BSZ * HSZ + 255) / 256, 256>>>();

    dim3 g1(G4 / 128, SSZ);   // (32, 256)
    gemm_xw_tc<<<g1, 256, P1_SMEM>>>(bxh, bhh);

    lstm_persist<<<GRID2, 256, P2_SMEM>>>();

    fc_out<<<BSZ, 256>>>(Wfc, bfc, out);
}